// round 13
// baseline (speedup 1.0000x reference)
#include <cuda_runtime.h>
#include <cuda_bf16.h>
#include <cstdint>

// ---------------------------------------------------------------------------
// B=64, L=512, Din=256, Dout=256, split=128
// gemm_pre via bf16 hi/lo split tensor-core GEMM (augmented K=768):
//   A' = [Ah | Al]  (bf16, 512 cols; block 2 of K remaps to block 0)
//   W'_g = [Wh ; Wh ; Wl]  (bf16, n-major, 768 rows)
//   G = A'' @ W' + bias  ==  AhWh + AlWh + AhWl   (~5e-6 rel err)
// gemm_mma is double-buffered: one __syncthreads per K-step.
// Recurrence: round-7 design (32 clusters x 4 CTAs, U in regs, mbarrier sync).
// ---------------------------------------------------------------------------

#define B_  64
#define L_  512
#define D_  256

// padded mt layout (recurrence)
#define MT_Q    68
#define MT_B    272
#define MT_PH   544

__device__ float g_G[(size_t)B_ * L_ * 768];                 // ~100.7 MB
__device__ float g_A[(size_t)B_ * L_];                       // 128 KB
__device__ float g_hist[(size_t)L_ * B_ * 128];              // 16 MB
__device__ __nv_bfloat16 g_A2[(size_t)B_ * L_ * 512];        // 32 MB  [m][512]
__device__ __nv_bfloat16 g_W2[(size_t)3 * 256 * 768];        // 1.2 MB [g][n][768]

// ---------------------------------------------------------------------------
// helpers
// ---------------------------------------------------------------------------
__device__ __forceinline__ unsigned long long ffma2(
    unsigned long long a, unsigned long long b, unsigned long long c)
{
    unsigned long long d;
    asm("fma.rn.f32x2 %0, %1, %2, %3;" : "=l"(d) : "l"(a), "l"(b), "l"(c));
    return d;
}
__device__ __forceinline__ unsigned long long pack2(float x, float y) {
    unsigned long long r;
    asm("mov.b64 %0, {%1, %2};" : "=l"(r) : "f"(x), "f"(y));
    return r;
}
__device__ __forceinline__ void unpack2(unsigned long long v, float& x, float& y) {
    asm("mov.b64 {%0, %1}, %2;" : "=f"(x), "=f"(y) : "l"(v));
}
__device__ __forceinline__ float hadd2(unsigned long long v) {
    float x, y; unpack2(v, x, y); return x + y;
}
__device__ __forceinline__ unsigned smem_u32(const void* p) {
    unsigned a;
    asm("{ .reg .u64 t; cvta.to.shared.u64 t, %1; cvt.u32.u64 %0, t; }" : "=r"(a) : "l"(p));
    return a;
}
__device__ __forceinline__ void mbar_init(unsigned mbar, unsigned cnt) {
    asm volatile("mbarrier.init.shared.b64 [%0], %1;" :: "r"(mbar), "r"(cnt) : "memory");
}
__device__ __forceinline__ void mbar_arrive_remote(unsigned laddr, unsigned rank) {
    asm volatile(
        "{ .reg .b32 ra;\n\t"
        "  mapa.shared::cluster.u32 ra, %0, %1;\n\t"
        "  mbarrier.arrive.release.cluster.shared::cluster.b64 _, [ra]; }"
        :: "r"(laddr), "r"(rank) : "memory");
}
__device__ __forceinline__ void mbar_wait_cta(unsigned mbar, unsigned parity) {
    asm volatile(
        "{\n\t.reg .pred P;\n\t"
        "WL%=:\n\t"
        "mbarrier.try_wait.parity.acquire.cta.shared::cta.b64 P, [%0], %1, 0x989680;\n\t"
        "@!P bra WL%=;\n\t}"
        :: "r"(mbar), "r"(parity) : "memory");
}
__device__ __forceinline__ void dsmem_st(unsigned laddr, unsigned rank, float v) {
    asm volatile(
        "{ .reg .b32 ra; mapa.shared::cluster.u32 ra, %0, %1;"
        "  st.shared::cluster.f32 [ra], %2; }"
        :: "r"(laddr), "r"(rank), "f"(v));
}
__device__ __forceinline__ void mma_bf16(
    float& c0, float& c1, float& c2, float& c3,
    unsigned a0, unsigned a1, unsigned a2, unsigned a3,
    unsigned b0, unsigned b1)
{
    asm("mma.sync.aligned.m16n8k16.row.col.f32.bf16.bf16.f32 "
        "{%0,%1,%2,%3}, {%4,%5,%6,%7}, {%8,%9}, {%0,%1,%2,%3};"
        : "+f"(c0), "+f"(c1), "+f"(c2), "+f"(c3)
        : "r"(a0), "r"(a1), "r"(a2), "r"(a3), "r"(b0), "r"(b1));
}

// ---------------------------------------------------------------------------
// Kernel 0: no-op, aligns ncu -s 5 window onto recur_kernel (6th launch).
// ---------------------------------------------------------------------------
__global__ void shift_kernel() {}

// ---------------------------------------------------------------------------
// Kernel 1a: A' = [Ah | Al].  grid 8192 x 256, each thread one float4.
// ---------------------------------------------------------------------------
__global__ void __launch_bounds__(256) convA(const float* __restrict__ inp)
{
    size_t idx = (size_t)blockIdx.x * 256 + threadIdx.x;   // float4 units
    float4 v = ((const float4*)inp)[idx];
    int m  = (int)(idx >> 6);
    int k4 = (int)(idx & 63) * 4;
    float a[4] = {v.x, v.y, v.z, v.w};
    __nv_bfloat16 h[4], l[4];
#pragma unroll
    for (int i = 0; i < 4; ++i) {
        h[i] = __float2bfloat16(a[i]);
        l[i] = __float2bfloat16(a[i] - __bfloat162float(h[i]));
    }
    __nv_bfloat16* row = g_A2 + (size_t)m * 512;
    *(__nv_bfloat162*)(row + k4)           = __halves2bfloat162(h[0], h[1]);
    *(__nv_bfloat162*)(row + k4 + 2)       = __halves2bfloat162(h[2], h[3]);
    *(__nv_bfloat162*)(row + 256 + k4)     = __halves2bfloat162(l[0], l[1]);
    *(__nv_bfloat162*)(row + 256 + k4 + 2) = __halves2bfloat162(l[2], l[3]);
}

// ---------------------------------------------------------------------------
// Kernel 1b: W'_g[n][k'] = [Wh ; Wh ; Wl] (n-major).  grid (3,16) x 256.
// ---------------------------------------------------------------------------
__global__ void __launch_bounds__(256) convW(
    const float* __restrict__ Wr, const float* __restrict__ Wz,
    const float* __restrict__ Wh)
{
    int g = blockIdx.x;
    const float* W = (g == 0) ? Wr : (g == 1) ? Wz : Wh;
    int n  = blockIdx.y * 16 + (threadIdx.x >> 4);
    int k0 = (threadIdx.x & 15) * 16;
    __nv_bfloat16* dst = g_W2 + ((size_t)g * 256 + n) * 768;
#pragma unroll
    for (int k = k0; k < k0 + 16; ++k) {
        float w = W[(size_t)k * 256 + n];
        __nv_bfloat16 hi = __float2bfloat16(w);
        __nv_bfloat16 lo = __float2bfloat16(w - __bfloat162float(hi));
        dst[k]       = hi;
        dst[256 + k] = hi;
        dst[512 + k] = lo;
    }
}

// ---------------------------------------------------------------------------
// Kernel 1c: G = A'' @ W' + bias.  bf16 mma.sync, tile 128x128, K'=768,
// double-buffered smem (ONE __syncthreads per K-step).
// A K-block 2 (k'>=512) remaps to A block 0 (Ah again).
// 8 warps: wm = warp>>2 (2), wn = warp&3 (4); warp tile 64x32.
// ---------------------------------------------------------------------------
__global__ void __launch_bounds__(256) gemm_mma(
    const float* __restrict__ br, const float* __restrict__ bz,
    const float* __restrict__ bh)
{
    __shared__ __nv_bfloat16 As[2][128 * 40];   // 128 rows x 32 (+8 pad)
    __shared__ __nv_bfloat16 Bs[2][128 * 40];

    const int gate  = blockIdx.x >> 1;
    const int ncol0 = (blockIdx.x & 1) * 128;
    const int mtile = blockIdx.y;
    const float* bias = (gate == 0) ? br : (gate == 1) ? bz : bh;

    const int tid  = threadIdx.x;
    const int warp = tid >> 5, lane = tid & 31;
    const int wm = warp >> 2, wn = warp & 3;
    const int gid = lane >> 2, tq = lane & 3;

    const __nv_bfloat16* Ag = g_A2 + (size_t)(mtile * 128) * 512;
    const __nv_bfloat16* Bg = g_W2 + ((size_t)gate * 256 + ncol0) * 768;

    const int r0 = tid >> 2,         o0 = (tid & 3) * 8;         // chunk 0
    const int r1 = (tid + 256) >> 2, o1 = ((tid + 256) & 3) * 8; // chunk 1

    float acc[4][4][4];
#pragma unroll
    for (int i = 0; i < 4; ++i)
#pragma unroll
        for (int jj = 0; jj < 4; ++jj)
#pragma unroll
            for (int q = 0; q < 4; ++q) acc[i][jj][q] = 0.f;

    uint4 av0, av1, bv0, bv1;
#define LDG_STEP(step) do {                                              \
        int kb = (step) * 32;                                            \
        int ka = (kb >= 512) ? kb - 512 : kb;                            \
        av0 = *(const uint4*)(Ag + (size_t)r0 * 512 + ka + o0);          \
        av1 = *(const uint4*)(Ag + (size_t)r1 * 512 + ka + o1);          \
        bv0 = *(const uint4*)(Bg + (size_t)r0 * 768 + kb + o0);          \
        bv1 = *(const uint4*)(Bg + (size_t)r1 * 768 + kb + o1);          \
    } while (0)
#define STS_STEP(buf) do {                                               \
        *(uint4*)&As[buf][r0 * 40 + o0] = av0;                           \
        *(uint4*)&As[buf][r1 * 40 + o1] = av1;                           \
        *(uint4*)&Bs[buf][r0 * 40 + o0] = bv0;                           \
        *(uint4*)&Bs[buf][r1 * 40 + o1] = bv1;                           \
    } while (0)

    LDG_STEP(0);
    STS_STEP(0);
    __syncthreads();

    for (int step = 0; step < 24; ++step) {
        const int buf = step & 1;
        if (step < 23) LDG_STEP(step + 1);

        const __nv_bfloat16* Ab = As[buf];
        const __nv_bfloat16* Bb = Bs[buf];
#pragma unroll
        for (int kk = 0; kk < 32; kk += 16) {
            unsigned bfr[4][2];
#pragma unroll
            for (int fn = 0; fn < 4; ++fn) {
                int nrow = wn * 32 + fn * 8 + gid;
                bfr[fn][0] = *(const unsigned*)&Bb[nrow * 40 + kk + tq * 2];
                bfr[fn][1] = *(const unsigned*)&Bb[nrow * 40 + kk + tq * 2 + 8];
            }
#pragma unroll
            for (int fm = 0; fm < 4; ++fm) {
                int ar = wm * 64 + fm * 16 + gid;
                unsigned a0 = *(const unsigned*)&Ab[ar * 40 + kk + tq * 2];
                unsigned a1 = *(const unsigned*)&Ab[(ar + 8) * 40 + kk + tq * 2];
                unsigned a2 = *(const unsigned*)&Ab[ar * 40 + kk + tq * 2 + 8];
                unsigned a3 = *(const unsigned*)&Ab[(ar + 8) * 40 + kk + tq * 2 + 8];
#pragma unroll
                for (int fn = 0; fn < 4; ++fn)
                    mma_bf16(acc[fm][fn][0], acc[fm][fn][1],
                             acc[fm][fn][2], acc[fm][fn][3],
                             a0, a1, a2, a3, bfr[fn][0], bfr[fn][1]);
            }
        }

        if (step < 23) {
            STS_STEP(buf ^ 1);
            __syncthreads();
        }
    }
#undef LDG_STEP
#undef STS_STEP

    // store with bias
#pragma unroll
    for (int fn = 0; fn < 4; ++fn) {
        int ngl = gate * 256 + ncol0 + wn * 32 + fn * 8 + tq * 2;   // G column
        float b0 = bias[ncol0 + wn * 32 + fn * 8 + tq * 2];
        float b1 = bias[ncol0 + wn * 32 + fn * 8 + tq * 2 + 1];
#pragma unroll
        for (int fm = 0; fm < 4; ++fm) {
            int m0 = mtile * 128 + wm * 64 + fm * 16 + gid;
            float2 lo = make_float2(acc[fm][fn][0] + b0, acc[fm][fn][1] + b1);
            float2 hi = make_float2(acc[fm][fn][2] + b0, acc[fm][fn][3] + b1);
            *(float2*)&g_G[(size_t)m0 * 768 + ngl]       = lo;
            *(float2*)&g_G[(size_t)(m0 + 8) * 768 + ngl] = hi;
        }
    }
}

// ---------------------------------------------------------------------------
// Kernel 2: a[m] = sigmoid(x[m] . (k1 - k2))
// ---------------------------------------------------------------------------
__global__ void __launch_bounds__(256) avals_kernel(
    const float* __restrict__ inp,
    const float* __restrict__ k1, const float* __restrict__ k2)
{
    const int warp = threadIdx.x >> 5, lane = threadIdx.x & 31;
    const int m = blockIdx.x * 8 + warp;
    const float* x = inp + (size_t)m * D_;
    float s = 0.f;
#pragma unroll
    for (int i = lane; i < D_; i += 32) s += x[i] * (k1[i] - k2[i]);
#pragma unroll
    for (int o = 16; o; o >>= 1) s += __shfl_xor_sync(0xFFFFFFFFu, s, o);
    if (lane == 0) g_A[m] = 1.f / (1.f + __expf(-s));
}

// ---------------------------------------------------------------------------
// Kernel 3: recurrence — round-7 design (best known: ~946 us).
// ---------------------------------------------------------------------------
__global__ void __launch_bounds__(256, 1) __cluster_dims__(4, 1, 1)
recur_kernel(const float* __restrict__ Ur, const float* __restrict__ Uz,
             const float* __restrict__ Uh, const int* __restrict__ ci,
             float* __restrict__ out)
{
    __shared__ __align__(16) float mts2[2 * MT_PH];     // [phase][b][padded k]
    __shared__ __align__(16) float a_s[2 * 512];        // [b][t]
    __shared__ __align__(16) int   ci_s[2 * 512];       // [b][t]
    __shared__ __align__(8)  unsigned long long mbar_s;

    const int tid  = threadIdx.x;
    const int rank = blockIdx.x & 3;
    const int grp  = blockIdx.x >> 2;
    const int b0   = grp * 2;
    const int dg0  = rank * 64;

    const int j  = (tid >> 2) & 63;
    const int kq = tid & 3;
    const int k0 = kq * 64;

    const bool act = (kq < 2);
    const int  b   = kq;
    const int  dg  = dg0 + j;
    const bool hi  = (dg >= 128);
    const int  dq  = dg - 128;
    const int  mtoff = dg + 4 * (dg >> 6);

    unsigned long long u0[32], u1[32], u2[32];
    {
        const float* pr = Ur + (size_t)k0 * D_ + dg;
        const float* pz = Uz + (size_t)k0 * D_ + dg;
        const float* ph = Uh + (size_t)k0 * D_ + dg;
#pragma unroll
        for (int i = 0; i < 32; ++i) {
            u0[i] = pack2(pr[(2 * i) * D_], pr[(2 * i + 1) * D_]);
            u1[i] = pack2(pz[(2 * i) * D_], pz[(2 * i + 1) * D_]);
            u2[i] = pack2(ph[(2 * i) * D_], ph[(2 * i + 1) * D_]);
        }
    }
    {
        const float4* ga = (const float4*)&g_A[(size_t)b0 * L_];
        const int4*   gc = (const int4*)  (ci + (size_t)b0 * L_);
        ((float4*)a_s)[tid] = ga[tid];
        ((int4*)ci_s)[tid]  = gc[tid];
    }
    for (int i = tid; i < 2 * MT_PH; i += 256) mts2[i] = 0.f;
    if (tid == 0) mbar_init(smem_u32(&mbar_s), 32);
    __syncthreads();
    asm volatile("barrier.cluster.arrive.aligned;" ::: "memory");
    asm volatile("barrier.cluster.wait.aligned;" ::: "memory");

    const unsigned mbar = smem_u32(&mbar_s);

    float gn0 = 0.f, gn1 = 0.f, gn2 = 0.f;
    float vc  = 0.f;
    if (act) {
        size_t gb = ((size_t)(b0 + b) * L_) * 768 + dg;
        gn0 = g_G[gb]; gn1 = g_G[gb + 256]; gn2 = g_G[gb + 512];
    }

    for (int t = 0; t < L_; ++t) {
        const int p = t & 1;

        unsigned long long a00 = 0ull, a01 = 0ull;
        unsigned long long a10 = 0ull, a11 = 0ull;
        unsigned long long a20 = 0ull, a21 = 0ull;
        {
            const float* base = &mts2[p * MT_PH];
            const ulonglong2* m0 = (const ulonglong2*)(base + MT_Q * kq);
            const ulonglong2* m1 = (const ulonglong2*)(base + MT_B + MT_Q * kq);
#pragma unroll
            for (int i = 0; i < 16; ++i) {
                ulonglong2 v0 = m0[i];
                ulonglong2 v1 = m1[i];
                a00 = ffma2(u0[2 * i], v0.x, a00);
                a01 = ffma2(u0[2 * i], v1.x, a01);
                a10 = ffma2(u1[2 * i], v0.x, a10);
                a11 = ffma2(u1[2 * i], v1.x, a11);
                a20 = ffma2(u2[2 * i], v0.x, a20);
                a21 = ffma2(u2[2 * i], v1.x, a21);
                a00 = ffma2(u0[2 * i + 1], v0.y, a00);
                a01 = ffma2(u0[2 * i + 1], v1.y, a01);
                a10 = ffma2(u1[2 * i + 1], v0.y, a10);
                a11 = ffma2(u1[2 * i + 1], v1.y, a11);
                a20 = ffma2(u2[2 * i + 1], v0.y, a20);
                a21 = ffma2(u2[2 * i + 1], v1.y, a21);
            }
        }
        float sr0 = hadd2(a00), sr1 = hadd2(a01);
        float sz0 = hadd2(a10), sz1 = hadd2(a11);
        float sh0 = hadd2(a20), sh1 = hadd2(a21);
#pragma unroll
        for (int o = 1; o <= 2; o <<= 1) {
            sr0 += __shfl_xor_sync(0xFFFFFFFFu, sr0, o);
            sr1 += __shfl_xor_sync(0xFFFFFFFFu, sr1, o);
            sz0 += __shfl_xor_sync(0xFFFFFFFFu, sz0, o);
            sz1 += __shfl_xor_sync(0xFFFFFFFFu, sz1, o);
            sh0 += __shfl_xor_sync(0xFFFFFFFFu, sh0, o);
            sh1 += __shfl_xor_sync(0xFFFFFFFFu, sh1, o);
        }

        float h = 0.f;
        const int tn = (t + 1 < L_) ? (t + 1) : (L_ - 1);
        if (act) {
            float Sr = b ? sr1 : sr0;
            float Sz = b ? sz1 : sz0;
            float Sh = b ? sh1 : sh0;
            float r  = 1.f / (1.f + __expf(-(gn0 + Sr)));
            float z  = 1.f / (1.f + __expf(-(gn1 + Sz)));
            float ti = gn2 + r * Sh;
            float th = 2.f / (1.f + __expf(-2.f * ti)) - 1.f;
            float mtd = mts2[p * MT_PH + b * MT_B + mtoff];
            h = (1.f - z) * mtd + z * th;

            float av = a_s[b * L_ + tn];
            float mtv;
            if (!hi) {
                mtv = av * h;
            } else {
                g_hist[((size_t)t * B_ + b0 + b) * 128 + dq] = h;
                int c1 = ci_s[b * L_ + tn];
                float cv = (c1 - 1 == t) ? h : vc;
                mtv = (1.f - av) * cv;
            }
            unsigned laddr = smem_u32(&mts2[(p ^ 1) * MT_PH + b * MT_B + mtoff]);
#pragma unroll
            for (int rr = 0; rr < 4; ++rr) dsmem_st(laddr, rr, mtv);
        }

        __syncwarp();
        if ((tid & 31) < 4) mbar_arrive_remote(mbar, tid & 31);

        if (act) {
            out[(((size_t)(b0 + b)) * L_ + t) * D_ + dg] = h;
            size_t gb = ((size_t)(b0 + b) * L_ + tn) * 768 + dg;
            gn0 = g_G[gb]; gn1 = g_G[gb + 256]; gn2 = g_G[gb + 512];
            if (hi) {
                int t2 = (t + 2 < L_) ? (t + 2) : (L_ - 1);
                int c2 = ci_s[b * L_ + t2];
                vc = 0.f;
                if (c2 > 0 && (c2 - 1) <= t)
                    vc = g_hist[((size_t)(c2 - 1) * B_ + b0 + b) * 128 + dq];
            }
        }

        mbar_wait_cta(mbar, p);
    }
}

// ---------------------------------------------------------------------------
// launch
// ---------------------------------------------------------------------------
extern "C" void kernel_launch(void* const* d_in, const int* in_sizes, int n_in,
                              void* d_out, int out_size)
{
    const float* inp = (const float*)d_in[0];
    const int*   ci  = (const int*)  d_in[1];
    const float* Wr  = (const float*)d_in[2];
    const float* br  = (const float*)d_in[3];
    const float* Ur  = (const float*)d_in[4];
    const float* Wz  = (const float*)d_in[5];
    const float* bz  = (const float*)d_in[6];
    const float* Uz  = (const float*)d_in[7];
    const float* Wh  = (const float*)d_in[8];
    const float* bh  = (const float*)d_in[9];
    const float* Uh  = (const float*)d_in[10];
    const float* k1  = (const float*)d_in[11];
    const float* k2  = (const float*)d_in[12];
    float* out = (float*)d_out;

    shift_kernel<<<1, 32>>>();                         // #1 (ncu align)
    convA<<<8192, 256>>>(inp);                         // #2
    convW<<<dim3(3, 16), 256>>>(Wr, Wz, Wh);           // #3
    gemm_mma<<<dim3(6, 256), 256>>>(br, bz, bh);       // #4
    avals_kernel<<<(B_ * L_) / 8, 256>>>(inp, k1, k2); // #5
    recur_kernel<<<128, 256>>>(Ur, Uz, Uh, ci, out);   // #6  <- ncu -s 5
}

// round 14
// speedup vs baseline: 1.0247x; 1.0247x over previous
#include <cuda_runtime.h>
#include <cuda_bf16.h>
#include <cstdint>

// ---------------------------------------------------------------------------
// B=64, L=512, Din=256, Dout=256, split=128
// gemm_pre via bf16 hi/lo split tensor-core GEMM (augmented K=768):
//   A' = [Ah | Al]  (bf16, 512 cols; K-block 2 remaps to block 0)
//   W'_g = [Wh ; Wh ; Wl]  (bf16, n-major, 768 rows)
//   G = A'' @ W' + bias  ==  AhWh + AlWh + AhWl   (~5e-6 rel err)
// gemm_mma: double-buffered, 2 CTAs/SM; blockIdx.x==6 slice computes avals.
// Recurrence: round-7 design (32 clusters x 4 CTAs, U in regs, mbarrier sync).
// ---------------------------------------------------------------------------

#define B_  64
#define L_  512
#define D_  256

// padded mt layout (recurrence)
#define MT_Q    68
#define MT_B    272
#define MT_PH   544

__device__ float g_G[(size_t)B_ * L_ * 768];                 // ~100.7 MB
__device__ float g_A[(size_t)B_ * L_];                       // 128 KB
__device__ float g_hist[(size_t)L_ * B_ * 128];              // 16 MB
__device__ __nv_bfloat16 g_A2[(size_t)B_ * L_ * 512];        // 32 MB  [m][512]
__device__ __nv_bfloat16 g_W2[(size_t)3 * 256 * 768];        // 1.2 MB [g][n][768]

// ---------------------------------------------------------------------------
// helpers
// ---------------------------------------------------------------------------
__device__ __forceinline__ unsigned long long ffma2(
    unsigned long long a, unsigned long long b, unsigned long long c)
{
    unsigned long long d;
    asm("fma.rn.f32x2 %0, %1, %2, %3;" : "=l"(d) : "l"(a), "l"(b), "l"(c));
    return d;
}
__device__ __forceinline__ unsigned long long pack2(float x, float y) {
    unsigned long long r;
    asm("mov.b64 %0, {%1, %2};" : "=l"(r) : "f"(x), "f"(y));
    return r;
}
__device__ __forceinline__ void unpack2(unsigned long long v, float& x, float& y) {
    asm("mov.b64 {%0, %1}, %2;" : "=f"(x), "=f"(y) : "l"(v));
}
__device__ __forceinline__ float hadd2(unsigned long long v) {
    float x, y; unpack2(v, x, y); return x + y;
}
__device__ __forceinline__ unsigned smem_u32(const void* p) {
    unsigned a;
    asm("{ .reg .u64 t; cvta.to.shared.u64 t, %1; cvt.u32.u64 %0, t; }" : "=r"(a) : "l"(p));
    return a;
}
__device__ __forceinline__ void mbar_init(unsigned mbar, unsigned cnt) {
    asm volatile("mbarrier.init.shared.b64 [%0], %1;" :: "r"(mbar), "r"(cnt) : "memory");
}
__device__ __forceinline__ void mbar_arrive_remote(unsigned laddr, unsigned rank) {
    asm volatile(
        "{ .reg .b32 ra;\n\t"
        "  mapa.shared::cluster.u32 ra, %0, %1;\n\t"
        "  mbarrier.arrive.release.cluster.shared::cluster.b64 _, [ra]; }"
        :: "r"(laddr), "r"(rank) : "memory");
}
__device__ __forceinline__ void mbar_wait_cta(unsigned mbar, unsigned parity) {
    asm volatile(
        "{\n\t.reg .pred P;\n\t"
        "WL%=:\n\t"
        "mbarrier.try_wait.parity.acquire.cta.shared::cta.b64 P, [%0], %1, 0x989680;\n\t"
        "@!P bra WL%=;\n\t}"
        :: "r"(mbar), "r"(parity) : "memory");
}
__device__ __forceinline__ void dsmem_st(unsigned laddr, unsigned rank, float v) {
    asm volatile(
        "{ .reg .b32 ra; mapa.shared::cluster.u32 ra, %0, %1;"
        "  st.shared::cluster.f32 [ra], %2; }"
        :: "r"(laddr), "r"(rank), "f"(v));
}
__device__ __forceinline__ void mma_bf16(
    float& c0, float& c1, float& c2, float& c3,
    unsigned a0, unsigned a1, unsigned a2, unsigned a3,
    unsigned b0, unsigned b1)
{
    asm("mma.sync.aligned.m16n8k16.row.col.f32.bf16.bf16.f32 "
        "{%0,%1,%2,%3}, {%4,%5,%6,%7}, {%8,%9}, {%0,%1,%2,%3};"
        : "+f"(c0), "+f"(c1), "+f"(c2), "+f"(c3)
        : "r"(a0), "r"(a1), "r"(a2), "r"(a3), "r"(b0), "r"(b1));
}

// ---------------------------------------------------------------------------
// Kernel 1a: A' = [Ah | Al].  grid 8192 x 256, each thread one float4.
// ---------------------------------------------------------------------------
__global__ void __launch_bounds__(256) convA(const float* __restrict__ inp)
{
    size_t idx = (size_t)blockIdx.x * 256 + threadIdx.x;   // float4 units
    float4 v = ((const float4*)inp)[idx];
    int m  = (int)(idx >> 6);
    int k4 = (int)(idx & 63) * 4;
    float a[4] = {v.x, v.y, v.z, v.w};
    __nv_bfloat16 h[4], l[4];
#pragma unroll
    for (int i = 0; i < 4; ++i) {
        h[i] = __float2bfloat16(a[i]);
        l[i] = __float2bfloat16(a[i] - __bfloat162float(h[i]));
    }
    __nv_bfloat16* row = g_A2 + (size_t)m * 512;
    *(__nv_bfloat162*)(row + k4)           = __halves2bfloat162(h[0], h[1]);
    *(__nv_bfloat162*)(row + k4 + 2)       = __halves2bfloat162(h[2], h[3]);
    *(__nv_bfloat162*)(row + 256 + k4)     = __halves2bfloat162(l[0], l[1]);
    *(__nv_bfloat162*)(row + 256 + k4 + 2) = __halves2bfloat162(l[2], l[3]);
}

// ---------------------------------------------------------------------------
// Kernel 1b: W'_g[n][k'] = [Wh ; Wh ; Wl] (n-major).  grid (3,16) x 256.
// ---------------------------------------------------------------------------
__global__ void __launch_bounds__(256) convW(
    const float* __restrict__ Wr, const float* __restrict__ Wz,
    const float* __restrict__ Wh)
{
    int g = blockIdx.x;
    const float* W = (g == 0) ? Wr : (g == 1) ? Wz : Wh;
    int n  = blockIdx.y * 16 + (threadIdx.x >> 4);
    int k0 = (threadIdx.x & 15) * 16;
    __nv_bfloat16* dst = g_W2 + ((size_t)g * 256 + n) * 768;
#pragma unroll
    for (int k = k0; k < k0 + 16; ++k) {
        float w = W[(size_t)k * 256 + n];
        __nv_bfloat16 hi = __float2bfloat16(w);
        __nv_bfloat16 lo = __float2bfloat16(w - __bfloat162float(hi));
        dst[k]       = hi;
        dst[256 + k] = hi;
        dst[512 + k] = lo;
    }
}

// ---------------------------------------------------------------------------
// Kernel 1c: G = A'' @ W' + bias.  bf16 mma.sync, tile 128x128, K'=768,
// double-buffered smem, 2 CTAs/SM. blockIdx.x==6 computes avals instead.
// ---------------------------------------------------------------------------
__global__ void __launch_bounds__(256, 2) gemm_mma(
    const float* __restrict__ inp,
    const float* __restrict__ k1, const float* __restrict__ k2,
    const float* __restrict__ br, const float* __restrict__ bz,
    const float* __restrict__ bh)
{
    __shared__ __nv_bfloat16 As[2][128 * 40];
    __shared__ __nv_bfloat16 Bs[2][128 * 40];

    const int mtile = blockIdx.y;
    const int tid   = threadIdx.x;
    const int warp  = tid >> 5, lane = tid & 31;

    // ---- avals slice: a[m] = sigmoid(x[m].(k1-k2)) for this mtile's rows ----
    if (blockIdx.x == 6) {
        for (int r = warp; r < 128; r += 8) {
            int m = mtile * 128 + r;
            const float* x = inp + (size_t)m * D_;
            float s = 0.f;
#pragma unroll
            for (int i = lane; i < D_; i += 32) s += x[i] * (k1[i] - k2[i]);
#pragma unroll
            for (int o = 16; o; o >>= 1) s += __shfl_xor_sync(0xFFFFFFFFu, s, o);
            if (lane == 0) g_A[m] = 1.f / (1.f + __expf(-s));
        }
        return;
    }

    const int gate  = blockIdx.x >> 1;
    const int ncol0 = (blockIdx.x & 1) * 128;
    const float* bias = (gate == 0) ? br : (gate == 1) ? bz : bh;

    const int wm = warp >> 2, wn = warp & 3;
    const int gid = lane >> 2, tq = lane & 3;

    const __nv_bfloat16* Ag = g_A2 + (size_t)(mtile * 128) * 512;
    const __nv_bfloat16* Bg = g_W2 + ((size_t)gate * 256 + ncol0) * 768;

    const int r0 = tid >> 2,         o0 = (tid & 3) * 8;
    const int r1 = (tid + 256) >> 2, o1 = ((tid + 256) & 3) * 8;

    float acc[4][4][4];
#pragma unroll
    for (int i = 0; i < 4; ++i)
#pragma unroll
        for (int jj = 0; jj < 4; ++jj)
#pragma unroll
            for (int q = 0; q < 4; ++q) acc[i][jj][q] = 0.f;

    uint4 av0, av1, bv0, bv1;
#define LDG_STEP(step) do {                                              \
        int kb = (step) * 32;                                            \
        int ka = (kb >= 512) ? kb - 512 : kb;                            \
        av0 = *(const uint4*)(Ag + (size_t)r0 * 512 + ka + o0);          \
        av1 = *(const uint4*)(Ag + (size_t)r1 * 512 + ka + o1);          \
        bv0 = *(const uint4*)(Bg + (size_t)r0 * 768 + kb + o0);          \
        bv1 = *(const uint4*)(Bg + (size_t)r1 * 768 + kb + o1);          \
    } while (0)
#define STS_STEP(buf) do {                                               \
        *(uint4*)&As[buf][r0 * 40 + o0] = av0;                           \
        *(uint4*)&As[buf][r1 * 40 + o1] = av1;                           \
        *(uint4*)&Bs[buf][r0 * 40 + o0] = bv0;                           \
        *(uint4*)&Bs[buf][r1 * 40 + o1] = bv1;                           \
    } while (0)

    LDG_STEP(0);
    STS_STEP(0);
    __syncthreads();

    for (int step = 0; step < 24; ++step) {
        const int buf = step & 1;
        if (step < 23) LDG_STEP(step + 1);

        const __nv_bfloat16* Ab = As[buf];
        const __nv_bfloat16* Bb = Bs[buf];
#pragma unroll
        for (int kk = 0; kk < 32; kk += 16) {
            unsigned bfr[4][2];
#pragma unroll
            for (int fn = 0; fn < 4; ++fn) {
                int nrow = wn * 32 + fn * 8 + gid;
                bfr[fn][0] = *(const unsigned*)&Bb[nrow * 40 + kk + tq * 2];
                bfr[fn][1] = *(const unsigned*)&Bb[nrow * 40 + kk + tq * 2 + 8];
            }
#pragma unroll
            for (int fm = 0; fm < 4; ++fm) {
                int ar = wm * 64 + fm * 16 + gid;
                unsigned a0 = *(const unsigned*)&Ab[ar * 40 + kk + tq * 2];
                unsigned a1 = *(const unsigned*)&Ab[(ar + 8) * 40 + kk + tq * 2];
                unsigned a2 = *(const unsigned*)&Ab[ar * 40 + kk + tq * 2 + 8];
                unsigned a3 = *(const unsigned*)&Ab[(ar + 8) * 40 + kk + tq * 2 + 8];
#pragma unroll
                for (int fn = 0; fn < 4; ++fn)
                    mma_bf16(acc[fm][fn][0], acc[fm][fn][1],
                             acc[fm][fn][2], acc[fm][fn][3],
                             a0, a1, a2, a3, bfr[fn][0], bfr[fn][1]);
            }
        }

        if (step < 23) {
            STS_STEP(buf ^ 1);
            __syncthreads();
        }
    }
#undef LDG_STEP
#undef STS_STEP

#pragma unroll
    for (int fn = 0; fn < 4; ++fn) {
        int ngl = gate * 256 + ncol0 + wn * 32 + fn * 8 + tq * 2;
        float b0 = bias[ncol0 + wn * 32 + fn * 8 + tq * 2];
        float b1 = bias[ncol0 + wn * 32 + fn * 8 + tq * 2 + 1];
#pragma unroll
        for (int fm = 0; fm < 4; ++fm) {
            int m0 = mtile * 128 + wm * 64 + fm * 16 + gid;
            float2 lo = make_float2(acc[fm][fn][0] + b0, acc[fm][fn][1] + b1);
            float2 hi = make_float2(acc[fm][fn][2] + b0, acc[fm][fn][3] + b1);
            *(float2*)&g_G[(size_t)m0 * 768 + ngl]       = lo;
            *(float2*)&g_G[(size_t)(m0 + 8) * 768 + ngl] = hi;
        }
    }
}

// ---------------------------------------------------------------------------
// Kernel 3: recurrence — round-7 design (best known: ~946 us). Unchanged.
// ---------------------------------------------------------------------------
__global__ void __launch_bounds__(256, 1) __cluster_dims__(4, 1, 1)
recur_kernel(const float* __restrict__ Ur, const float* __restrict__ Uz,
             const float* __restrict__ Uh, const int* __restrict__ ci,
             float* __restrict__ out)
{
    __shared__ __align__(16) float mts2[2 * MT_PH];     // [phase][b][padded k]
    __shared__ __align__(16) float a_s[2 * 512];        // [b][t]
    __shared__ __align__(16) int   ci_s[2 * 512];       // [b][t]
    __shared__ __align__(8)  unsigned long long mbar_s;

    const int tid  = threadIdx.x;
    const int rank = blockIdx.x & 3;
    const int grp  = blockIdx.x >> 2;
    const int b0   = grp * 2;
    const int dg0  = rank * 64;

    const int j  = (tid >> 2) & 63;
    const int kq = tid & 3;
    const int k0 = kq * 64;

    const bool act = (kq < 2);
    const int  b   = kq;
    const int  dg  = dg0 + j;
    const bool hi  = (dg >= 128);
    const int  dq  = dg - 128;
    const int  mtoff = dg + 4 * (dg >> 6);

    unsigned long long u0[32], u1[32], u2[32];
    {
        const float* pr = Ur + (size_t)k0 * D_ + dg;
        const float* pz = Uz + (size_t)k0 * D_ + dg;
        const float* ph = Uh + (size_t)k0 * D_ + dg;
#pragma unroll
        for (int i = 0; i < 32; ++i) {
            u0[i] = pack2(pr[(2 * i) * D_], pr[(2 * i + 1) * D_]);
            u1[i] = pack2(pz[(2 * i) * D_], pz[(2 * i + 1) * D_]);
            u2[i] = pack2(ph[(2 * i) * D_], ph[(2 * i + 1) * D_]);
        }
    }
    {
        const float4* ga = (const float4*)&g_A[(size_t)b0 * L_];
        const int4*   gc = (const int4*)  (ci + (size_t)b0 * L_);
        ((float4*)a_s)[tid] = ga[tid];
        ((int4*)ci_s)[tid]  = gc[tid];
    }
    for (int i = tid; i < 2 * MT_PH; i += 256) mts2[i] = 0.f;
    if (tid == 0) mbar_init(smem_u32(&mbar_s), 32);
    __syncthreads();
    asm volatile("barrier.cluster.arrive.aligned;" ::: "memory");
    asm volatile("barrier.cluster.wait.aligned;" ::: "memory");

    const unsigned mbar = smem_u32(&mbar_s);

    float gn0 = 0.f, gn1 = 0.f, gn2 = 0.f;
    float vc  = 0.f;
    if (act) {
        size_t gb = ((size_t)(b0 + b) * L_) * 768 + dg;
        gn0 = g_G[gb]; gn1 = g_G[gb + 256]; gn2 = g_G[gb + 512];
    }

    for (int t = 0; t < L_; ++t) {
        const int p = t & 1;

        unsigned long long a00 = 0ull, a01 = 0ull;
        unsigned long long a10 = 0ull, a11 = 0ull;
        unsigned long long a20 = 0ull, a21 = 0ull;
        {
            const float* base = &mts2[p * MT_PH];
            const ulonglong2* m0 = (const ulonglong2*)(base + MT_Q * kq);
            const ulonglong2* m1 = (const ulonglong2*)(base + MT_B + MT_Q * kq);
#pragma unroll
            for (int i = 0; i < 16; ++i) {
                ulonglong2 v0 = m0[i];
                ulonglong2 v1 = m1[i];
                a00 = ffma2(u0[2 * i], v0.x, a00);
                a01 = ffma2(u0[2 * i], v1.x, a01);
                a10 = ffma2(u1[2 * i], v0.x, a10);
                a11 = ffma2(u1[2 * i], v1.x, a11);
                a20 = ffma2(u2[2 * i], v0.x, a20);
                a21 = ffma2(u2[2 * i], v1.x, a21);
                a00 = ffma2(u0[2 * i + 1], v0.y, a00);
                a01 = ffma2(u0[2 * i + 1], v1.y, a01);
                a10 = ffma2(u1[2 * i + 1], v0.y, a10);
                a11 = ffma2(u1[2 * i + 1], v1.y, a11);
                a20 = ffma2(u2[2 * i + 1], v0.y, a20);
                a21 = ffma2(u2[2 * i + 1], v1.y, a21);
            }
        }
        float sr0 = hadd2(a00), sr1 = hadd2(a01);
        float sz0 = hadd2(a10), sz1 = hadd2(a11);
        float sh0 = hadd2(a20), sh1 = hadd2(a21);
#pragma unroll
        for (int o = 1; o <= 2; o <<= 1) {
            sr0 += __shfl_xor_sync(0xFFFFFFFFu, sr0, o);
            sr1 += __shfl_xor_sync(0xFFFFFFFFu, sr1, o);
            sz0 += __shfl_xor_sync(0xFFFFFFFFu, sz0, o);
            sz1 += __shfl_xor_sync(0xFFFFFFFFu, sz1, o);
            sh0 += __shfl_xor_sync(0xFFFFFFFFu, sh0, o);
            sh1 += __shfl_xor_sync(0xFFFFFFFFu, sh1, o);
        }

        float h = 0.f;
        const int tn = (t + 1 < L_) ? (t + 1) : (L_ - 1);
        if (act) {
            float Sr = b ? sr1 : sr0;
            float Sz = b ? sz1 : sz0;
            float Sh = b ? sh1 : sh0;
            float r  = 1.f / (1.f + __expf(-(gn0 + Sr)));
            float z  = 1.f / (1.f + __expf(-(gn1 + Sz)));
            float ti = gn2 + r * Sh;
            float th = 2.f / (1.f + __expf(-2.f * ti)) - 1.f;
            float mtd = mts2[p * MT_PH + b * MT_B + mtoff];
            h = (1.f - z) * mtd + z * th;

            float av = a_s[b * L_ + tn];
            float mtv;
            if (!hi) {
                mtv = av * h;
            } else {
                g_hist[((size_t)t * B_ + b0 + b) * 128 + dq] = h;
                int c1 = ci_s[b * L_ + tn];
                float cv = (c1 - 1 == t) ? h : vc;
                mtv = (1.f - av) * cv;
            }
            unsigned laddr = smem_u32(&mts2[(p ^ 1) * MT_PH + b * MT_B + mtoff]);
#pragma unroll
            for (int rr = 0; rr < 4; ++rr) dsmem_st(laddr, rr, mtv);
        }

        __syncwarp();
        if ((tid & 31) < 4) mbar_arrive_remote(mbar, tid & 31);

        if (act) {
            out[(((size_t)(b0 + b)) * L_ + t) * D_ + dg] = h;
            size_t gb = ((size_t)(b0 + b) * L_ + tn) * 768 + dg;
            gn0 = g_G[gb]; gn1 = g_G[gb + 256]; gn2 = g_G[gb + 512];
            if (hi) {
                int t2 = (t + 2 < L_) ? (t + 2) : (L_ - 1);
                int c2 = ci_s[b * L_ + t2];
                vc = 0.f;
                if (c2 > 0 && (c2 - 1) <= t)
                    vc = g_hist[((size_t)(c2 - 1) * B_ + b0 + b) * 128 + dq];
            }
        }

        mbar_wait_cta(mbar, p);
    }
}

// ---------------------------------------------------------------------------
// launch
// ---------------------------------------------------------------------------
extern "C" void kernel_launch(void* const* d_in, const int* in_sizes, int n_in,
                              void* d_out, int out_size)
{
    const float* inp = (const float*)d_in[0];
    const int*   ci  = (const int*)  d_in[1];
    const float* Wr  = (const float*)d_in[2];
    const float* br  = (const float*)d_in[3];
    const float* Ur  = (const float*)d_in[4];
    const float* Wz  = (const float*)d_in[5];
    const float* bz  = (const float*)d_in[6];
    const float* Uz  = (const float*)d_in[7];
    const float* Wh  = (const float*)d_in[8];
    const float* bh  = (const float*)d_in[9];
    const float* Uh  = (const float*)d_in[10];
    const float* k1  = (const float*)d_in[11];
    const float* k2  = (const float*)d_in[12];
    float* out = (float*)d_out;

    convA<<<8192, 256>>>(inp);                              // #1
    convW<<<dim3(3, 16), 256>>>(Wr, Wz, Wh);                // #2
    gemm_mma<<<dim3(7, 256), 256>>>(inp, k1, k2, br, bz, bh); // #3 (+avals)
    recur_kernel<<<128, 256>>>(Ur, Uz, Uh, ci, out);        // #4 <- profiled
}

// round 16
// speedup vs baseline: 1.1596x; 1.1317x over previous
#include <cuda_runtime.h>
#include <cuda_bf16.h>
#include <cstdint>

// ---------------------------------------------------------------------------
// B=64, L=512, Din=256, Dout=256, split=128
// gemm_pre via bf16 hi/lo split tensor-core GEMM (augmented K=768).
// Recurrence: round-7 dataflow; per-step sync = ONE local __syncthreads +
// 4 remote arrives from threads 0..3.  Each CTA's barrier receives exactly
// 4 arrives/step (one per source CTA) -> mbar count = 4.
// ---------------------------------------------------------------------------

#define B_  64
#define L_  512
#define D_  256

// padded mt layout (recurrence)
#define MT_Q    68
#define MT_B    272
#define MT_PH   544

__device__ float g_G[(size_t)B_ * L_ * 768];                 // ~100.7 MB
__device__ float g_A[(size_t)B_ * L_];                       // 128 KB
__device__ float g_hist[(size_t)L_ * B_ * 128];              // 16 MB
__device__ __nv_bfloat16 g_A2[(size_t)B_ * L_ * 512];        // 32 MB  [m][512]
__device__ __nv_bfloat16 g_W2[(size_t)3 * 256 * 768];        // 1.2 MB [g][n][768]

// ---------------------------------------------------------------------------
// helpers
// ---------------------------------------------------------------------------
__device__ __forceinline__ unsigned long long ffma2(
    unsigned long long a, unsigned long long b, unsigned long long c)
{
    unsigned long long d;
    asm("fma.rn.f32x2 %0, %1, %2, %3;" : "=l"(d) : "l"(a), "l"(b), "l"(c));
    return d;
}
__device__ __forceinline__ unsigned long long pack2(float x, float y) {
    unsigned long long r;
    asm("mov.b64 %0, {%1, %2};" : "=l"(r) : "f"(x), "f"(y));
    return r;
}
__device__ __forceinline__ void unpack2(unsigned long long v, float& x, float& y) {
    asm("mov.b64 {%0, %1}, %2;" : "=f"(x), "=f"(y) : "l"(v));
}
__device__ __forceinline__ float hadd2(unsigned long long v) {
    float x, y; unpack2(v, x, y); return x + y;
}
__device__ __forceinline__ unsigned smem_u32(const void* p) {
    unsigned a;
    asm("{ .reg .u64 t; cvta.to.shared.u64 t, %1; cvt.u32.u64 %0, t; }" : "=r"(a) : "l"(p));
    return a;
}
__device__ __forceinline__ void mbar_init(unsigned mbar, unsigned cnt) {
    asm volatile("mbarrier.init.shared.b64 [%0], %1;" :: "r"(mbar), "r"(cnt) : "memory");
}
__device__ __forceinline__ void mbar_arrive_remote(unsigned laddr, unsigned rank) {
    asm volatile(
        "{ .reg .b32 ra;\n\t"
        "  mapa.shared::cluster.u32 ra, %0, %1;\n\t"
        "  mbarrier.arrive.release.cluster.shared::cluster.b64 _, [ra]; }"
        :: "r"(laddr), "r"(rank) : "memory");
}
__device__ __forceinline__ void mbar_wait_cta(unsigned mbar, unsigned parity) {
    asm volatile(
        "{\n\t.reg .pred P;\n\t"
        "WL%=:\n\t"
        "mbarrier.try_wait.parity.acquire.cta.shared::cta.b64 P, [%0], %1, 0x989680;\n\t"
        "@!P bra WL%=;\n\t}"
        :: "r"(mbar), "r"(parity) : "memory");
}
__device__ __forceinline__ void dsmem_st(unsigned laddr, unsigned rank, float v) {
    asm volatile(
        "{ .reg .b32 ra; mapa.shared::cluster.u32 ra, %0, %1;"
        "  st.shared::cluster.f32 [ra], %2; }"
        :: "r"(laddr), "r"(rank), "f"(v));
}
__device__ __forceinline__ void mma_bf16(
    float& c0, float& c1, float& c2, float& c3,
    unsigned a0, unsigned a1, unsigned a2, unsigned a3,
    unsigned b0, unsigned b1)
{
    asm("mma.sync.aligned.m16n8k16.row.col.f32.bf16.bf16.f32 "
        "{%0,%1,%2,%3}, {%4,%5,%6,%7}, {%8,%9}, {%0,%1,%2,%3};"
        : "+f"(c0), "+f"(c1), "+f"(c2), "+f"(c3)
        : "r"(a0), "r"(a1), "r"(a2), "r"(a3), "r"(b0), "r"(b1));
}

// ---------------------------------------------------------------------------
// Kernel 1a: A' = [Ah | Al].  grid 8192 x 256, each thread one float4.
// ---------------------------------------------------------------------------
__global__ void __launch_bounds__(256) convA(const float* __restrict__ inp)
{
    size_t idx = (size_t)blockIdx.x * 256 + threadIdx.x;   // float4 units
    float4 v = ((const float4*)inp)[idx];
    int m  = (int)(idx >> 6);
    int k4 = (int)(idx & 63) * 4;
    float a[4] = {v.x, v.y, v.z, v.w};
    __nv_bfloat16 h[4], l[4];
#pragma unroll
    for (int i = 0; i < 4; ++i) {
        h[i] = __float2bfloat16(a[i]);
        l[i] = __float2bfloat16(a[i] - __bfloat162float(h[i]));
    }
    __nv_bfloat16* row = g_A2 + (size_t)m * 512;
    *(__nv_bfloat162*)(row + k4)           = __halves2bfloat162(h[0], h[1]);
    *(__nv_bfloat162*)(row + k4 + 2)       = __halves2bfloat162(h[2], h[3]);
    *(__nv_bfloat162*)(row + 256 + k4)     = __halves2bfloat162(l[0], l[1]);
    *(__nv_bfloat162*)(row + 256 + k4 + 2) = __halves2bfloat162(l[2], l[3]);
}

// ---------------------------------------------------------------------------
// Kernel 1b: W'_g[n][k'] = [Wh ; Wh ; Wl] (n-major).  grid (3,16) x 256.
// ---------------------------------------------------------------------------
__global__ void __launch_bounds__(256) convW(
    const float* __restrict__ Wr, const float* __restrict__ Wz,
    const float* __restrict__ Wh)
{
    int g = blockIdx.x;
    const float* W = (g == 0) ? Wr : (g == 1) ? Wz : Wh;
    int n  = blockIdx.y * 16 + (threadIdx.x >> 4);
    int k0 = (threadIdx.x & 15) * 16;
    __nv_bfloat16* dst = g_W2 + ((size_t)g * 256 + n) * 768;
#pragma unroll
    for (int k = k0; k < k0 + 16; ++k) {
        float w = W[(size_t)k * 256 + n];
        __nv_bfloat16 hi = __float2bfloat16(w);
        __nv_bfloat16 lo = __float2bfloat16(w - __bfloat162float(hi));
        dst[k]       = hi;
        dst[256 + k] = hi;
        dst[512 + k] = lo;
    }
}

// ---------------------------------------------------------------------------
// Kernel 1c: G = A'' @ W' + bias.  bf16 mma.sync, tile 128x128, K'=768,
// double-buffered smem, 2 CTAs/SM. blockIdx.x==6 computes avals instead.
// ---------------------------------------------------------------------------
__global__ void __launch_bounds__(256, 2) gemm_mma(
    const float* __restrict__ inp,
    const float* __restrict__ k1, const float* __restrict__ k2,
    const float* __restrict__ br, const float* __restrict__ bz,
    const float* __restrict__ bh)
{
    __shared__ __nv_bfloat16 As[2][128 * 40];
    __shared__ __nv_bfloat16 Bs[2][128 * 40];

    const int mtile = blockIdx.y;
    const int tid   = threadIdx.x;
    const int warp  = tid >> 5, lane = tid & 31;

    // ---- avals slice: a[m] = sigmoid(x[m].(k1-k2)) for this mtile's rows ----
    if (blockIdx.x == 6) {
        for (int r = warp; r < 128; r += 8) {
            int m = mtile * 128 + r;
            const float* x = inp + (size_t)m * D_;
            float s = 0.f;
#pragma unroll
            for (int i = lane; i < D_; i += 32) s += x[i] * (k1[i] - k2[i]);
#pragma unroll
            for (int o = 16; o; o >>= 1) s += __shfl_xor_sync(0xFFFFFFFFu, s, o);
            if (lane == 0) g_A[m] = 1.f / (1.f + __expf(-s));
        }
        return;
    }

    const int gate  = blockIdx.x >> 1;
    const int ncol0 = (blockIdx.x & 1) * 128;
    const float* bias = (gate == 0) ? br : (gate == 1) ? bz : bh;

    const int wm = warp >> 2, wn = warp & 3;
    const int gid = lane >> 2, tq = lane & 3;

    const __nv_bfloat16* Ag = g_A2 + (size_t)(mtile * 128) * 512;
    const __nv_bfloat16* Bg = g_W2 + ((size_t)gate * 256 + ncol0) * 768;

    const int r0 = tid >> 2,         o0 = (tid & 3) * 8;
    const int r1 = (tid + 256) >> 2, o1 = ((tid + 256) & 3) * 8;

    float acc[4][4][4];
#pragma unroll
    for (int i = 0; i < 4; ++i)
#pragma unroll
        for (int jj = 0; jj < 4; ++jj)
#pragma unroll
            for (int q = 0; q < 4; ++q) acc[i][jj][q] = 0.f;

    uint4 av0, av1, bv0, bv1;
#define LDG_STEP(step) do {                                              \
        int kb = (step) * 32;                                            \
        int ka = (kb >= 512) ? kb - 512 : kb;                            \
        av0 = *(const uint4*)(Ag + (size_t)r0 * 512 + ka + o0);          \
        av1 = *(const uint4*)(Ag + (size_t)r1 * 512 + ka + o1);          \
        bv0 = *(const uint4*)(Bg + (size_t)r0 * 768 + kb + o0);          \
        bv1 = *(const uint4*)(Bg + (size_t)r1 * 768 + kb + o1);          \
    } while (0)
#define STS_STEP(buf) do {                                               \
        *(uint4*)&As[buf][r0 * 40 + o0] = av0;                           \
        *(uint4*)&As[buf][r1 * 40 + o1] = av1;                           \
        *(uint4*)&Bs[buf][r0 * 40 + o0] = bv0;                           \
        *(uint4*)&Bs[buf][r1 * 40 + o1] = bv1;                           \
    } while (0)

    LDG_STEP(0);
    STS_STEP(0);
    __syncthreads();

    for (int step = 0; step < 24; ++step) {
        const int buf = step & 1;
        if (step < 23) LDG_STEP(step + 1);

        const __nv_bfloat16* Ab = As[buf];
        const __nv_bfloat16* Bb = Bs[buf];
#pragma unroll
        for (int kk = 0; kk < 32; kk += 16) {
            unsigned bfr[4][2];
#pragma unroll
            for (int fn = 0; fn < 4; ++fn) {
                int nrow = wn * 32 + fn * 8 + gid;
                bfr[fn][0] = *(const unsigned*)&Bb[nrow * 40 + kk + tq * 2];
                bfr[fn][1] = *(const unsigned*)&Bb[nrow * 40 + kk + tq * 2 + 8];
            }
#pragma unroll
            for (int fm = 0; fm < 4; ++fm) {
                int ar = wm * 64 + fm * 16 + gid;
                unsigned a0 = *(const unsigned*)&Ab[ar * 40 + kk + tq * 2];
                unsigned a1 = *(const unsigned*)&Ab[(ar + 8) * 40 + kk + tq * 2];
                unsigned a2 = *(const unsigned*)&Ab[ar * 40 + kk + tq * 2 + 8];
                unsigned a3 = *(const unsigned*)&Ab[(ar + 8) * 40 + kk + tq * 2 + 8];
#pragma unroll
                for (int fn = 0; fn < 4; ++fn)
                    mma_bf16(acc[fm][fn][0], acc[fm][fn][1],
                             acc[fm][fn][2], acc[fm][fn][3],
                             a0, a1, a2, a3, bfr[fn][0], bfr[fn][1]);
            }
        }

        if (step < 23) {
            STS_STEP(buf ^ 1);
            __syncthreads();
        }
    }
#undef LDG_STEP
#undef STS_STEP

#pragma unroll
    for (int fn = 0; fn < 4; ++fn) {
        int ngl = gate * 256 + ncol0 + wn * 32 + fn * 8 + tq * 2;
        float b0 = bias[ncol0 + wn * 32 + fn * 8 + tq * 2];
        float b1 = bias[ncol0 + wn * 32 + fn * 8 + tq * 2 + 1];
#pragma unroll
        for (int fm = 0; fm < 4; ++fm) {
            int m0 = mtile * 128 + wm * 64 + fm * 16 + gid;
            float2 lo = make_float2(acc[fm][fn][0] + b0, acc[fm][fn][1] + b1);
            float2 hi = make_float2(acc[fm][fn][2] + b0, acc[fm][fn][3] + b1);
            *(float2*)&g_G[(size_t)m0 * 768 + ngl]       = lo;
            *(float2*)&g_G[(size_t)(m0 + 8) * 768 + ngl] = hi;
        }
    }
}

// ---------------------------------------------------------------------------
// Kernel 3: recurrence. Round-7 dataflow; arrive protocol:
// after eltwise+DSMEM push: __syncthreads, then threads 0..3 arrive remotely
// (one per rank).  Each CTA's barrier receives 4 arrives/step -> count = 4.
// ---------------------------------------------------------------------------
__global__ void __launch_bounds__(256, 1) __cluster_dims__(4, 1, 1)
recur_kernel(const float* __restrict__ Ur, const float* __restrict__ Uz,
             const float* __restrict__ Uh, const int* __restrict__ ci,
             float* __restrict__ out)
{
    __shared__ __align__(16) float mts2[2 * MT_PH];     // [phase][b][padded k]
    __shared__ __align__(16) float a_s[2 * 512];        // [b][t]
    __shared__ __align__(16) int   ci_s[2 * 512];       // [b][t]
    __shared__ __align__(8)  unsigned long long mbar_s;

    const int tid  = threadIdx.x;
    const int rank = blockIdx.x & 3;
    const int grp  = blockIdx.x >> 2;
    const int b0   = grp * 2;
    const int dg0  = rank * 64;

    const int j  = (tid >> 2) & 63;
    const int kq = tid & 3;
    const int k0 = kq * 64;

    const bool act = (kq < 2);
    const int  b   = kq;
    const int  dg  = dg0 + j;
    const bool hi  = (dg >= 128);
    const int  dq  = dg - 128;
    const int  mtoff = dg + 4 * (dg >> 6);

    unsigned long long u0[32], u1[32], u2[32];
    {
        const float* pr = Ur + (size_t)k0 * D_ + dg;
        const float* pz = Uz + (size_t)k0 * D_ + dg;
        const float* ph = Uh + (size_t)k0 * D_ + dg;
#pragma unroll
        for (int i = 0; i < 32; ++i) {
            u0[i] = pack2(pr[(2 * i) * D_], pr[(2 * i + 1) * D_]);
            u1[i] = pack2(pz[(2 * i) * D_], pz[(2 * i + 1) * D_]);
            u2[i] = pack2(ph[(2 * i) * D_], ph[(2 * i + 1) * D_]);
        }
    }
    {
        const float4* ga = (const float4*)&g_A[(size_t)b0 * L_];
        const int4*   gc = (const int4*)  (ci + (size_t)b0 * L_);
        ((float4*)a_s)[tid] = ga[tid];
        ((int4*)ci_s)[tid]  = gc[tid];
    }
    for (int i = tid; i < 2 * MT_PH; i += 256) mts2[i] = 0.f;
    if (tid == 0) mbar_init(smem_u32(&mbar_s), 4);
    __syncthreads();
    asm volatile("barrier.cluster.arrive.aligned;" ::: "memory");
    asm volatile("barrier.cluster.wait.aligned;" ::: "memory");

    const unsigned mbar = smem_u32(&mbar_s);

    float gn0 = 0.f, gn1 = 0.f, gn2 = 0.f;
    float vc  = 0.f;
    if (act) {
        size_t gb = ((size_t)(b0 + b) * L_) * 768 + dg;
        gn0 = g_G[gb]; gn1 = g_G[gb + 256]; gn2 = g_G[gb + 512];
    }

    for (int t = 0; t < L_; ++t) {
        const int p = t & 1;

        unsigned long long a00 = 0ull, a01 = 0ull;
        unsigned long long a10 = 0ull, a11 = 0ull;
        unsigned long long a20 = 0ull, a21 = 0ull;
        {
            const float* base = &mts2[p * MT_PH];
            const ulonglong2* m0 = (const ulonglong2*)(base + MT_Q * kq);
            const ulonglong2* m1 = (const ulonglong2*)(base + MT_B + MT_Q * kq);
#pragma unroll
            for (int i = 0; i < 16; ++i) {
                ulonglong2 v0 = m0[i];
                ulonglong2 v1 = m1[i];
                a00 = ffma2(u0[2 * i], v0.x, a00);
                a01 = ffma2(u0[2 * i], v1.x, a01);
                a10 = ffma2(u1[2 * i], v0.x, a10);
                a11 = ffma2(u1[2 * i], v1.x, a11);
                a20 = ffma2(u2[2 * i], v0.x, a20);
                a21 = ffma2(u2[2 * i], v1.x, a21);
                a00 = ffma2(u0[2 * i + 1], v0.y, a00);
                a01 = ffma2(u0[2 * i + 1], v1.y, a01);
                a10 = ffma2(u1[2 * i + 1], v0.y, a10);
                a11 = ffma2(u1[2 * i + 1], v1.y, a11);
                a20 = ffma2(u2[2 * i + 1], v0.y, a20);
                a21 = ffma2(u2[2 * i + 1], v1.y, a21);
            }
        }
        float sr0 = hadd2(a00), sr1 = hadd2(a01);
        float sz0 = hadd2(a10), sz1 = hadd2(a11);
        float sh0 = hadd2(a20), sh1 = hadd2(a21);
#pragma unroll
        for (int o = 1; o <= 2; o <<= 1) {
            sr0 += __shfl_xor_sync(0xFFFFFFFFu, sr0, o);
            sr1 += __shfl_xor_sync(0xFFFFFFFFu, sr1, o);
            sz0 += __shfl_xor_sync(0xFFFFFFFFu, sz0, o);
            sz1 += __shfl_xor_sync(0xFFFFFFFFu, sz1, o);
            sh0 += __shfl_xor_sync(0xFFFFFFFFu, sh0, o);
            sh1 += __shfl_xor_sync(0xFFFFFFFFu, sh1, o);
        }

        float h = 0.f;
        const int tn = (t + 1 < L_) ? (t + 1) : (L_ - 1);
        if (act) {
            float Sr = b ? sr1 : sr0;
            float Sz = b ? sz1 : sz0;
            float Sh = b ? sh1 : sh0;
            float r  = 1.f / (1.f + __expf(-(gn0 + Sr)));
            float z  = 1.f / (1.f + __expf(-(gn1 + Sz)));
            float ti = gn2 + r * Sh;
            float th = 2.f / (1.f + __expf(-2.f * ti)) - 1.f;
            float mtd = mts2[p * MT_PH + b * MT_B + mtoff];
            h = (1.f - z) * mtd + z * th;

            float av = a_s[b * L_ + tn];
            float mtv;
            if (!hi) {
                mtv = av * h;
            } else {
                g_hist[((size_t)t * B_ + b0 + b) * 128 + dq] = h;
                int c1 = ci_s[b * L_ + tn];
                float cv = (c1 - 1 == t) ? h : vc;
                mtv = (1.f - av) * cv;
            }
            unsigned laddr = smem_u32(&mts2[(p ^ 1) * MT_PH + b * MT_B + mtoff]);
#pragma unroll
            for (int rr = 0; rr < 4; ++rr) dsmem_st(laddr, rr, mtv);
        }

        // one local barrier, then 4 remote arrives total (threads 0..3)
        __syncthreads();
        if (tid < 4) mbar_arrive_remote(mbar, tid);

        // off-critical-path: output, prefetches
        if (act) {
            out[(((size_t)(b0 + b)) * L_ + t) * D_ + dg] = h;
            size_t gb = ((size_t)(b0 + b) * L_ + tn) * 768 + dg;
            gn0 = g_G[gb]; gn1 = g_G[gb + 256]; gn2 = g_G[gb + 512];
            if (hi) {
                int t2 = (t + 2 < L_) ? (t + 2) : (L_ - 1);
                int c2 = ci_s[b * L_ + t2];
                vc = 0.f;
                if (c2 > 0 && (c2 - 1) <= t)
                    vc = g_hist[((size_t)(c2 - 1) * B_ + b0 + b) * 128 + dq];
            }
        }

        mbar_wait_cta(mbar, p);
    }
}

// ---------------------------------------------------------------------------
// launch
// ---------------------------------------------------------------------------
extern "C" void kernel_launch(void* const* d_in, const int* in_sizes, int n_in,
                              void* d_out, int out_size)
{
    const float* inp = (const float*)d_in[0];
    const int*   ci  = (const int*)  d_in[1];
    const float* Wr  = (const float*)d_in[2];
    const float* br  = (const float*)d_in[3];
    const float* Ur  = (const float*)d_in[4];
    const float* Wz  = (const float*)d_in[5];
    const float* bz  = (const float*)d_in[6];
    const float* Uz  = (const float*)d_in[7];
    const float* Wh  = (const float*)d_in[8];
    const float* bh  = (const float*)d_in[9];
    const float* Uh  = (const float*)d_in[10];
    const float* k1  = (const float*)d_in[11];
    const float* k2  = (const float*)d_in[12];
    float* out = (float*)d_out;

    convA<<<8192, 256>>>(inp);                                // #1
    convW<<<dim3(3, 16), 256>>>(Wr, Wz, Wh);                  // #2
    gemm_mma<<<dim3(7, 256), 256>>>(inp, k1, k2, br, bz, bh); // #3 (+avals)
    recur_kernel<<<128, 256>>>(Ur, Uz, Uh, ci, out);          // #4 <- profiled
}